// round 15
// baseline (speedup 1.0000x reference)
#include <cuda_runtime.h>
#include <cuda_fp16.h>
#include <math.h>
#include <stdint.h>

#define Nn 100000
#define Ee 1600000
#define Dd 128
#define Ll 3
#define CAPB 96
#define MAX_OV 8192
#define NDTOT (Nn * Dd)
#define NTILES 782
#define NSM 148

// ---------------- device scratch ----------------
static __device__ __half A_half[NDTOT];               // lin1(y), fp16
static __device__ float H_buf[NDTOT];
static __device__ int   cnt_buf[Nn];
static __device__ int   bucket_buf[Nn * CAPB];
static __device__ int   ov_src[MAX_OV];
static __device__ int   ov_dst[MAX_OV];
static __device__ int   ov_cnt;
static __device__ int   g_is64;
static __device__ double g_sum, g_sumsq;
static __device__ __half Y_half[NDTOT];               // fp16 Y for GEMM A operand
// per layer 3 tiles [n][k] fp16: W1,W2,W3 (transposed)
static __device__ __half Wsp_buf[Ll * 3 * 128 * 128];

__device__ __forceinline__ uint32_t s2u(const void* p) {
    return (uint32_t)__cvta_generic_to_shared(p);
}

// ---------------- init ----------------
__global__ void init_kernel(const int* __restrict__ ei) {
    int i = blockIdx.x * blockDim.x + threadIdx.x;
    if (i < Nn) cnt_buf[i] = 0;
    if (i == 0) {
        ov_cnt = 0;
        int all0 = 1;
        for (int k = 0; k < 128; k++) {
            if (ei[2 * k + 1] != 0) { all0 = 0; break; }
        }
        g_is64 = all0;
    }
}

__device__ __forceinline__ int fetch_idx(const int* __restrict__ ei, int pos, int is64) {
    return is64 ? ei[2 * pos] : ei[pos];
}

__global__ void zero_stats() {
    if (threadIdx.x == 0 && blockIdx.x == 0) { g_sum = 0.0; g_sumsq = 0.0; }
}

// ------- build CSR buckets + convert Y + weights to fp16 ------------------
__global__ void build_prep(const int* __restrict__ ei,
                           const float* __restrict__ Y,
                           const float* __restrict__ W1,
                           const float* __restrict__ W2,
                           const float* __restrict__ W3) {
    int idx = blockIdx.x * blockDim.x + threadIdx.x;
    if (idx < Ee) {
        int is64 = g_is64;
        int src = fetch_idx(ei, idx, is64);
        int dst = fetch_idx(ei, Ee + idx, is64);
        int pos = atomicAdd(&cnt_buf[dst], 1);
        if (pos < CAPB) {
            bucket_buf[(size_t)dst * CAPB + pos] = src;
        } else {
            int o = atomicAdd(&ov_cnt, 1);
            if (o < MAX_OV) { ov_src[o] = src; ov_dst[o] = dst; }
        }
    }
    if (idx < NDTOT / 2) {
        float2 v = *reinterpret_cast<const float2*>(Y + 2 * idx);
        *reinterpret_cast<__half2*>(Y_half + 2 * idx) = __floats2half2_rn(v.x, v.y);
    }
    if (idx < Ll * 3 * 16384) {
        int lw = idx >> 14;
        int rem = idx & 16383;
        int k = rem >> 7, n = rem & 127;
        int l = lw / 3, w = lw % 3;   // w: 0=W1 1=W2 2=W3
        const float* W = (w == 0) ? W1 : (w == 1) ? W2 : W3;
        float v = W[(size_t)l * 16384 + rem];
        Wsp_buf[((size_t)l * 3 + w) * 16384 + (size_t)n * 128 + k] = __float2half_rn(v);
    }
}

// ======================= HMMA helpers ==========================
__device__ __forceinline__ void mma_f16(float* d, const uint32_t* a, const uint32_t* b) {
    asm volatile("mma.sync.aligned.m16n8k16.row.col.f32.f16.f16.f32 "
        "{%0,%1,%2,%3}, {%4,%5,%6,%7}, {%8,%9}, {%0,%1,%2,%3};"
        : "+f"(d[0]), "+f"(d[1]), "+f"(d[2]), "+f"(d[3])
        : "r"(a[0]), "r"(a[1]), "r"(a[2]), "r"(a[3]), "r"(b[0]), "r"(b[1]));
}
__device__ __forceinline__ void ldsm4(uint32_t* r, uint32_t addr) {
    asm volatile("ldmatrix.sync.aligned.m8n8.x4.shared.b16 {%0,%1,%2,%3}, [%4];"
        : "=r"(r[0]), "=r"(r[1]), "=r"(r[2]), "=r"(r[3]) : "r"(addr));
}
__device__ __forceinline__ void cpa16(uint32_t dst, const void* src) {
    asm volatile("cp.async.cg.shared.global [%0], [%1], 16;"
                 :: "r"(dst), "l"(src) : "memory");
}
#define CPA_COMMIT() asm volatile("cp.async.commit_group;" ::: "memory")
#define CPA_WAIT(n)  asm volatile("cp.async.wait_group %0;" :: "n"(n) : "memory")

#define TSTRIDE 272u
#define TILE_BYTES (128u * TSTRIDE)
#define T_OFF(i) ((uint32_t)(i) * TILE_BYTES)
#define BIAS_OFF (5u * TILE_BYTES)      // 1KB: b1[128], b3[128] fp32
#define G_SMEM (5u * TILE_BYTES + 1024u)  // 175104
#define NTHR 512

// ===== persistent fused GEMM: 3 pipelined single-acc passes ===============
// smem tiles: 0=W1 1=W2 2=W3 3=Ybuf0 4=Ybuf1; then biases
__global__ void __launch_bounds__(NTHR, 1) gemm_fused(int layer,
                                                      const float* __restrict__ b1,
                                                      const float* __restrict__ b3) {
    extern __shared__ char smem[];
    uint32_t sb = s2u(smem);
    int tid = threadIdx.x, lane = tid & 31, wid = tid >> 5;
    int warp_m = wid & 3, warp_n = wid >> 2;      // 4 x 4 warps, warp tile 32x32

    if (blockIdx.x == 0 && tid == 0) { g_sum = 0.0; g_sumsq = 0.0; }

    // ---- weights: one cp.async group ----
    const __half* wbp = Wsp_buf + (size_t)layer * 3 * 16384;
#pragma unroll
    for (int tIdx = 0; tIdx < 3; tIdx++) {
        const __half* g = wbp + (size_t)tIdx * 16384;
        uint32_t off = T_OFF(tIdx);
        for (int i = tid; i < 2048; i += NTHR) {
            int n = i >> 4, c = i & 15;
            cpa16(sb + off + (uint32_t)n * TSTRIDE + (uint32_t)c * 16u,
                  g + (size_t)n * 128 + c * 8);
        }
    }
    CPA_COMMIT();

    // ---- biases to smem (once) ----
    if (tid < 128) {
        *reinterpret_cast<float*>(smem + BIAS_OFF + tid * 4)       = __ldg(b1 + tid);
        *reinterpret_cast<float*>(smem + BIAS_OFF + 512 + tid * 4) = __ldg(b3 + tid);
    }

// copy Y tile rows [base, base+128) into smem buffer (clamped source rows)
#define COPY_Y(bufsel, baseRow)                                                 \
    do {                                                                        \
        uint32_t _off = T_OFF(3 + (bufsel));                                    \
        for (int i = tid; i < 2048; i += NTHR) {                                \
            int n = i >> 4, c = i & 15;                                         \
            int r = (baseRow) + n;                                              \
            if (r >= Nn) r = Nn - 1;                                            \
            cpa16(sb + _off + (uint32_t)n * TSTRIDE + (uint32_t)c * 16u,        \
                  Y_half + (size_t)r * 128 + c * 8);                            \
        }                                                                       \
        CPA_COMMIT();                                                           \
    } while (0)

    COPY_Y(0, blockIdx.x * 128);

    // ldmatrix addressing
    uint32_t a_row = (uint32_t)(lane & 15);
    uint32_t a_hi  = (uint32_t)(lane >> 4) * 16u;
    uint32_t a_off0 = ((uint32_t)(warp_m * 32) + a_row) * TSTRIDE + a_hi;
    uint32_t a_off1 = ((uint32_t)(warp_m * 32 + 16) + a_row) * TSTRIDE + a_hi;
    uint32_t b_row = (uint32_t)((lane & 7) + ((lane >> 4) << 3));
    uint32_t b_hi  = (uint32_t)((lane >> 3) & 1) * 16u;
    uint32_t b_off0 = ((uint32_t)(warp_n * 32) + b_row) * TSTRIDE + b_hi;
    uint32_t b_off1 = ((uint32_t)(warp_n * 32 + 16) + b_row) * TSTRIDE + b_hi;

    int rloc = warp_m * 32 + (lane >> 2);
    int nbase = warp_n * 32 + (lane & 3) * 2;

// fully pipelined single-accumulator GEMM pass over weight tile TIDX
#define GEMM_PASS(acc, TIDX)                                                    \
    do {                                                                        \
        uint32_t yc[2][4], bc[2][4], yn[2][4], bn[2][4];                        \
        ldsm4(yc[0], ya + a_off0);                                              \
        ldsm4(yc[1], ya + a_off1);                                              \
        ldsm4(bc[0], sb + T_OFF(TIDX) + b_off0);                                \
        ldsm4(bc[1], sb + T_OFF(TIDX) + b_off1);                                \
        _Pragma("unroll")                                                       \
        for (int k0 = 0; k0 < 8; k0++) {                                        \
            if (k0 < 7) {                                                       \
                uint32_t kb = (uint32_t)(k0 + 1) * 32u;                         \
                ldsm4(yn[0], ya + a_off0 + kb);                                 \
                ldsm4(yn[1], ya + a_off1 + kb);                                 \
                ldsm4(bn[0], sb + T_OFF(TIDX) + b_off0 + kb);                   \
                ldsm4(bn[1], sb + T_OFF(TIDX) + b_off1 + kb);                   \
            }                                                                   \
            _Pragma("unroll")                                                   \
            for (int f = 0; f < 2; f++) {                                       \
                mma_f16(acc[f][0], yc[f], bc[0] + 0);                           \
                mma_f16(acc[f][1], yc[f], bc[0] + 2);                           \
                mma_f16(acc[f][2], yc[f], bc[1] + 0);                           \
                mma_f16(acc[f][3], yc[f], bc[1] + 2);                           \
            }                                                                   \
            _Pragma("unroll")                                                   \
            for (int q = 0; q < 4; q++) {                                       \
                yc[0][q] = yn[0][q]; yc[1][q] = yn[1][q];                       \
                bc[0][q] = bn[0][q]; bc[1][q] = bn[1][q];                       \
            }                                                                   \
        }                                                                       \
    } while (0)

    int p = 0;
    for (int t = blockIdx.x; t < NTILES; t += NSM) {
        int base = t * 128;
        int nxt = t + NSM;

        int issued = 0;
        if (nxt < NTILES) { COPY_Y(p ^ 1, nxt * 128); issued = 1; }
        if (issued) CPA_WAIT(1); else CPA_WAIT(0);
        __syncthreads();                    // Y buf p (weights, biases) visible

        uint32_t ya = sb + T_OFF(3 + p);
        int row[4];
        bool ok[4];
#pragma unroll
        for (int j = 0; j < 4; j++) { row[j] = base + rloc + j * 8; ok[j] = row[j] < Nn; }

        // ================= pass A: acc1 = Y@W1 (pipelined) ==================
        {
            float acc1[2][4][4];
#pragma unroll
            for (int f = 0; f < 2; f++)
#pragma unroll
                for (int ni = 0; ni < 4; ni++)
#pragma unroll
                    for (int j = 0; j < 4; j++) acc1[f][ni][j] = 0.f;

            GEMM_PASS(acc1, 0);

            // epilogue A: A_half = acc1 + b1 (bias via smem)
#pragma unroll
            for (int f = 0; f < 2; f++)
#pragma unroll
                for (int half = 0; half < 2; half++) {
                    int j = 2 * f + half;
                    if (!ok[j]) continue;
                    __half* ap = A_half + (size_t)row[j] * 128;
#pragma unroll
                    for (int ni = 0; ni < 4; ni++) {
                        int n = nbase + ni * 8;
                        float2 v1 = *reinterpret_cast<const float2*>(smem + BIAS_OFF + n * 4);
                        *reinterpret_cast<__half2*>(ap + n) =
                            __floats2half2_rn(acc1[f][ni][half * 2 + 0] + v1.x,
                                              acc1[f][ni][half * 2 + 1] + v1.y);
                    }
                }
        }

        // ======= pass B1: acc2 = Y@W2 (pipelined); B2: acc3 = Y@W3 ==========
        {
            float acc2[2][4][4];
#pragma unroll
            for (int f = 0; f < 2; f++)
#pragma unroll
                for (int ni = 0; ni < 4; ni++)
#pragma unroll
                    for (int j = 0; j < 4; j++) acc2[f][ni][j] = 0.f;

            GEMM_PASS(acc2, 1);

            float acc3[2][4][4];
#pragma unroll
            for (int f = 0; f < 2; f++)
#pragma unroll
                for (int ni = 0; ni < 4; ni++)
#pragma unroll
                    for (int j = 0; j < 4; j++) acc3[f][ni][j] = 0.f;

            // pass B2: unpipelined (acc2 live)
#pragma unroll
            for (int k0 = 0; k0 < 8; k0++) {
                uint32_t kb = (uint32_t)k0 * 32u;
                uint32_t yh[2][4], ch0[4], ch1[4];
                ldsm4(yh[0], ya + a_off0 + kb);
                ldsm4(yh[1], ya + a_off1 + kb);
                ldsm4(ch0, sb + T_OFF(2) + b_off0 + kb);
                ldsm4(ch1, sb + T_OFF(2) + b_off1 + kb);
#pragma unroll
                for (int f = 0; f < 2; f++) {
                    mma_f16(acc3[f][0], yh[f], ch0 + 0);
                    mma_f16(acc3[f][1], yh[f], ch0 + 2);
                    mma_f16(acc3[f][2], yh[f], ch1 + 0);
                    mma_f16(acc3[f][3], yh[f], ch1 + 2);
                }
            }

            // epilogue B: H = acc3 + b3 - deg*acc2 (bias via smem)
#pragma unroll
            for (int f = 0; f < 2; f++)
#pragma unroll
                for (int half = 0; half < 2; half++) {
                    int j = 2 * f + half;
                    if (!ok[j]) continue;
                    float dg = (float)cnt_buf[row[j]];
                    float* hp = H_buf + (size_t)row[j] * 128;
#pragma unroll
                    for (int ni = 0; ni < 4; ni++) {
                        int n = nbase + ni * 8;
                        float2 v3 = *reinterpret_cast<const float2*>(smem + BIAS_OFF + 512 + n * 4);
                        float2 o;
                        o.x = acc3[f][ni][half * 2 + 0] + v3.x - dg * acc2[f][ni][half * 2 + 0];
                        o.y = acc3[f][ni][half * 2 + 1] + v3.y - dg * acc2[f][ni][half * 2 + 1];
                        *reinterpret_cast<float2*>(hp + n) = o;
                    }
                }
        }

        __syncthreads();                    // reads of buf p done before overwrite
        p ^= 1;
    }
#undef COPY_Y
#undef GEMM_PASS
}

// --- gather: 4-deep pipelined rows + int4 index loads; fp32 fused stats ---
__global__ void gather_kernel() {
    int tid = threadIdx.x;
    int gw = (blockIdx.x * 256 + tid) >> 5;          // 12500*8 = 100000 exact
    int lane = tid & 31;
    int c = cnt_buf[gw];
    if (c > CAPB) c = CAPB;
    const int4* bk4 = reinterpret_cast<const int4*>(bucket_buf + (size_t)gw * CAPB);
    const uint2* ab = reinterpret_cast<const uint2*>(A_half);
    const uint2 z = make_uint2(0u, 0u);

#define ROW(i) __ldg(ab + (size_t)(i) * 32 + lane)

    float4 acc = make_float4(0.f, 0.f, 0.f, 0.f);
    int4 idx = (c > 0) ? __ldg(bk4) : make_int4(0, 0, 0, 0);
    uint2 v0 = (0 < c) ? ROW(idx.x) : z;
    uint2 v1 = (1 < c) ? ROW(idx.y) : z;
    uint2 v2 = (2 < c) ? ROW(idx.z) : z;
    uint2 v3 = (3 < c) ? ROW(idx.w) : z;

    for (int e = 0; e < c; e += 4) {
        int4 nidx = (e + 4 < c) ? __ldg(bk4 + (e >> 2) + 1) : make_int4(0, 0, 0, 0);
        uint2 c0 = v0, c1 = v1, c2 = v2, c3 = v3;
        v0 = (e + 4 < c) ? ROW(nidx.x) : z;
        v1 = (e + 5 < c) ? ROW(nidx.y) : z;
        v2 = (e + 6 < c) ? ROW(nidx.z) : z;
        v3 = (e + 7 < c) ? ROW(nidx.w) : z;
        float2 a;
        a = __half22float2(*reinterpret_cast<__half2*>(&c0.x)); acc.x += a.x; acc.y += a.y;
        a = __half22float2(*reinterpret_cast<__half2*>(&c0.y)); acc.z += a.x; acc.w += a.y;
        a = __half22float2(*reinterpret_cast<__half2*>(&c1.x)); acc.x += a.x; acc.y += a.y;
        a = __half22float2(*reinterpret_cast<__half2*>(&c1.y)); acc.z += a.x; acc.w += a.y;
        a = __half22float2(*reinterpret_cast<__half2*>(&c2.x)); acc.x += a.x; acc.y += a.y;
        a = __half22float2(*reinterpret_cast<__half2*>(&c2.y)); acc.z += a.x; acc.w += a.y;
        a = __half22float2(*reinterpret_cast<__half2*>(&c3.x)); acc.x += a.x; acc.y += a.y;
        a = __half22float2(*reinterpret_cast<__half2*>(&c3.y)); acc.z += a.x; acc.w += a.y;
    }
#undef ROW

    float4* hp = reinterpret_cast<float4*>(H_buf + (size_t)gw * 128) + lane;
    float4 h = *hp;
    h.x += acc.x; h.y += acc.y; h.z += acc.z; h.w += acc.w;
    *hp = h;

    float s  = h.x + h.y + h.z + h.w;
    float ss = h.x * h.x + h.y * h.y + h.z * h.z + h.w * h.w;
#pragma unroll
    for (int o = 16; o > 0; o >>= 1) {
        s  += __shfl_down_sync(0xffffffffu, s, o);
        ss += __shfl_down_sync(0xffffffffu, ss, o);
    }
    __shared__ float sh[2][8];
    int w = tid >> 5;
    if (lane == 0) { sh[0][w] = s; sh[1][w] = ss; }
    __syncthreads();
    if (tid == 0) {
        float ts = 0.f, tss = 0.f;
#pragma unroll
        for (int i = 0; i < 8; i++) { ts += sh[0][i]; tss += sh[1][i]; }
        atomicAdd(&g_sum, (double)ts);
        atomicAdd(&g_sumsq, (double)tss);
    }
}

// ---------------- overflow edges (ov_cnt==0 on this dataset) --------------
__global__ void overflow_fix() {
    int m = ov_cnt;
    if (m > MAX_OV) m = MAX_OV;
    int lane = threadIdx.x & 31;
    int w = threadIdx.x >> 5;
    for (int e = w; e < m; e += 8) {
        int src = ov_src[e], dst = ov_dst[e];
        const __half* ap = A_half + (size_t)src * 128;
        float* hp = H_buf + (size_t)dst * 128;
        for (int k = lane; k < 128; k += 32) atomicAdd(&hp[k], __half2float(ap[k]));
    }
}

// -- normalize + affine + leaky_relu + residual + fp16 store ---------------
__global__ void final_update(const float* __restrict__ lw, const float* __restrict__ lb,
                             const float* __restrict__ yin, float* __restrict__ yout,
                             int do_split) {
    double M = (double)NDTOT;
    double mean = g_sum / M;
    double var = g_sumsq / M - mean * mean;
    if (var < 0.0) var = 0.0;
    float inv = 1.0f / ((float)sqrt(var) + 1e-5f);
    float mf = (float)mean;

    int idx = blockIdx.x * blockDim.x + threadIdx.x;
    int stride = gridDim.x * blockDim.x;
    const float4* h4 = reinterpret_cast<const float4*>(H_buf);
    const float4* y4 = reinterpret_cast<const float4*>(yin);
    float4* o4 = reinterpret_cast<float4*>(yout);
    for (int i = idx; i < NDTOT / 4; i += stride) {
        int d = (i * 4) & 127;
        float4 w = *reinterpret_cast<const float4*>(lw + d);
        float4 b = *reinterpret_cast<const float4*>(lb + d);
        float4 h = h4[i];
        float4 y = y4[i];
        float t;
        float4 o;
        t = (h.x - mf) * inv; t = t * w.x + b.x; t = (t >= 0.f) ? t : 0.01f * t; o.x = y.x + t;
        t = (h.y - mf) * inv; t = t * w.y + b.y; t = (t >= 0.f) ? t : 0.01f * t; o.y = y.y + t;
        t = (h.z - mf) * inv; t = t * w.z + b.z; t = (t >= 0.f) ? t : 0.01f * t; o.z = y.z + t;
        t = (h.w - mf) * inv; t = t * w.w + b.w; t = (t >= 0.f) ? t : 0.01f * t; o.w = y.w + t;
        o4[i] = o;
        if (do_split) {
            __half2* yp = reinterpret_cast<__half2*>(Y_half + 4 * i);
            yp[0] = __floats2half2_rn(o.x, o.y);
            yp[1] = __floats2half2_rn(o.z, o.w);
        }
    }
}

// ---------------------------------------------------------------------------
extern "C" void kernel_launch(void* const* d_in, const int* in_sizes, int n_in,
                              void* d_out, int out_size) {
    const float* y0 = (const float*)d_in[0];
    const int*   ei = (const int*)d_in[1];
    const float* W1 = (const float*)d_in[2];
    const float* b1 = (const float*)d_in[3];
    const float* W2 = (const float*)d_in[4];
    const float* W3 = (const float*)d_in[5];
    const float* b3 = (const float*)d_in[6];
    const float* lw = (const float*)d_in[7];
    const float* lb = (const float*)d_in[8];
    float* yout = (float*)d_out;

    (void)in_sizes; (void)n_in; (void)out_size;

    cudaFuncSetAttribute(gemm_fused, cudaFuncAttributeMaxDynamicSharedMemorySize, G_SMEM);

    init_kernel<<<(Nn + 255) / 256, 256>>>(ei);                            // #1
    build_prep<<<(NDTOT / 2 + 255) / 256, 256>>>(ei, y0, W1, W2, W3);      // #2
    zero_stats<<<1, 32>>>();                                               // #3

    for (int l = 0; l < Ll; l++) {
        const float* yin = (l == 0) ? y0 : yout;
        gemm_fused<<<NSM, NTHR, G_SMEM>>>(l, b1 + (size_t)l * Dd,
                                          b3 + (size_t)l * Dd);            // #4 = profiled (l=0)
        gather_kernel<<<(Nn + 7) / 8, 256>>>();
        overflow_fix<<<1, 256>>>();
        final_update<<<1024, 256>>>(lw + (size_t)l * Dd, lb + (size_t)l * Dd, yin, yout,
                                    (l + 1 < Ll) ? 1 : 0);
    }
}

// round 16
// speedup vs baseline: 1.0812x; 1.0812x over previous
#include <cuda_runtime.h>
#include <cuda_fp16.h>
#include <math.h>
#include <stdint.h>

#define Nn 100000
#define Ee 1600000
#define Dd 128
#define Ll 3
#define CAPB 96
#define MAX_OV 8192
#define NDTOT (Nn * Dd)
#define NTILES 782
#define NSM 148

// ---------------- device scratch ----------------
static __device__ __half A_half[NDTOT];               // lin1(y), fp16
static __device__ float H_buf[NDTOT];
static __device__ int   cnt_buf[Nn];
static __device__ int   bucket_buf[Nn * CAPB];
static __device__ int   ov_src[MAX_OV];
static __device__ int   ov_dst[MAX_OV];
static __device__ int   ov_cnt;
static __device__ int   g_is64;
static __device__ double g_sum, g_sumsq;
static __device__ __half Y_half[NDTOT];               // fp16 Y for GEMM A operand
// per layer 3 tiles [n][k] fp16: W1,W2,W3 (transposed)
static __device__ __half Wsp_buf[Ll * 3 * 128 * 128];

__device__ __forceinline__ uint32_t s2u(const void* p) {
    return (uint32_t)__cvta_generic_to_shared(p);
}

// ---------------- init ----------------
__global__ void init_kernel(const int* __restrict__ ei) {
    int i = blockIdx.x * blockDim.x + threadIdx.x;
    if (i < Nn) cnt_buf[i] = 0;
    if (i == 0) {
        ov_cnt = 0;
        int all0 = 1;
        for (int k = 0; k < 128; k++) {
            if (ei[2 * k + 1] != 0) { all0 = 0; break; }
        }
        g_is64 = all0;
    }
}

__device__ __forceinline__ int fetch_idx(const int* __restrict__ ei, int pos, int is64) {
    return is64 ? ei[2 * pos] : ei[pos];
}

// ------- build CSR buckets + convert Y + weights to fp16 ------------------
__global__ void build_prep(const int* __restrict__ ei,
                           const float* __restrict__ Y,
                           const float* __restrict__ W1,
                           const float* __restrict__ W2,
                           const float* __restrict__ W3) {
    int idx = blockIdx.x * blockDim.x + threadIdx.x;
    if (idx < Ee) {
        int is64 = g_is64;
        int src = fetch_idx(ei, idx, is64);
        int dst = fetch_idx(ei, Ee + idx, is64);
        int pos = atomicAdd(&cnt_buf[dst], 1);
        if (pos < CAPB) {
            bucket_buf[(size_t)dst * CAPB + pos] = src;
        } else {
            int o = atomicAdd(&ov_cnt, 1);
            if (o < MAX_OV) { ov_src[o] = src; ov_dst[o] = dst; }
        }
    }
    if (idx < NDTOT / 2) {
        float2 v = *reinterpret_cast<const float2*>(Y + 2 * idx);
        *reinterpret_cast<__half2*>(Y_half + 2 * idx) = __floats2half2_rn(v.x, v.y);
    }
    if (idx < Ll * 3 * 16384) {
        int lw = idx >> 14;
        int rem = idx & 16383;
        int k = rem >> 7, n = rem & 127;
        int l = lw / 3, w = lw % 3;   // w: 0=W1 1=W2 2=W3
        const float* W = (w == 0) ? W1 : (w == 1) ? W2 : W3;
        float v = W[(size_t)l * 16384 + rem];
        Wsp_buf[((size_t)l * 3 + w) * 16384 + (size_t)n * 128 + k] = __float2half_rn(v);
    }
}

// ======================= HMMA helpers ==========================
__device__ __forceinline__ void mma_f16(float* d, const uint32_t* a, const uint32_t* b) {
    asm volatile("mma.sync.aligned.m16n8k16.row.col.f32.f16.f16.f32 "
        "{%0,%1,%2,%3}, {%4,%5,%6,%7}, {%8,%9}, {%0,%1,%2,%3};"
        : "+f"(d[0]), "+f"(d[1]), "+f"(d[2]), "+f"(d[3])
        : "r"(a[0]), "r"(a[1]), "r"(a[2]), "r"(a[3]), "r"(b[0]), "r"(b[1]));
}
__device__ __forceinline__ void ldsm4(uint32_t* r, uint32_t addr) {
    asm volatile("ldmatrix.sync.aligned.m8n8.x4.shared.b16 {%0,%1,%2,%3}, [%4];"
        : "=r"(r[0]), "=r"(r[1]), "=r"(r[2]), "=r"(r[3]) : "r"(addr));
}
__device__ __forceinline__ void cpa16(uint32_t dst, const void* src) {
    asm volatile("cp.async.cg.shared.global [%0], [%1], 16;"
                 :: "r"(dst), "l"(src) : "memory");
}
#define CPA_COMMIT() asm volatile("cp.async.commit_group;" ::: "memory")
#define CPA_WAIT(n)  asm volatile("cp.async.wait_group %0;" :: "n"(n) : "memory")

#define TSTRIDE 272u
#define TILE_BYTES (128u * TSTRIDE)
#define T_OFF(i) ((uint32_t)(i) * TILE_BYTES)
#define BIAS_OFF (5u * TILE_BYTES)      // 1KB: b1[128], b3[128] fp32
#define G_SMEM (5u * TILE_BYTES + 1024u)  // 175104
#define NTHR 512

// ===== persistent fused GEMM (round-14, measured 49.5us) ===================
// smem tiles: 0=W1 1=W2 2=W3 3=Ybuf0 4=Ybuf1; then biases
__global__ void __launch_bounds__(NTHR, 1) gemm_fused(int layer,
                                                      const float* __restrict__ b1,
                                                      const float* __restrict__ b3) {
    extern __shared__ char smem[];
    uint32_t sb = s2u(smem);
    int tid = threadIdx.x, lane = tid & 31, wid = tid >> 5;
    int warp_m = wid & 3, warp_n = wid >> 2;      // 4 x 4 warps, warp tile 32x32

    if (blockIdx.x == 0 && tid == 0) { g_sum = 0.0; g_sumsq = 0.0; }

    // ---- weights: one cp.async group ----
    const __half* wbp = Wsp_buf + (size_t)layer * 3 * 16384;
#pragma unroll
    for (int tIdx = 0; tIdx < 3; tIdx++) {
        const __half* g = wbp + (size_t)tIdx * 16384;
        uint32_t off = T_OFF(tIdx);
        for (int i = tid; i < 2048; i += NTHR) {
            int n = i >> 4, c = i & 15;
            cpa16(sb + off + (uint32_t)n * TSTRIDE + (uint32_t)c * 16u,
                  g + (size_t)n * 128 + c * 8);
        }
    }
    CPA_COMMIT();

    // ---- biases to smem (once) ----
    if (tid < 128) {
        *reinterpret_cast<float*>(smem + BIAS_OFF + tid * 4)       = __ldg(b1 + tid);
        *reinterpret_cast<float*>(smem + BIAS_OFF + 512 + tid * 4) = __ldg(b3 + tid);
    }

// copy Y tile rows [base, base+128) into smem buffer (clamped source rows)
#define COPY_Y(bufsel, baseRow)                                                 \
    do {                                                                        \
        uint32_t _off = T_OFF(3 + (bufsel));                                    \
        for (int i = tid; i < 2048; i += NTHR) {                                \
            int n = i >> 4, c = i & 15;                                         \
            int r = (baseRow) + n;                                              \
            if (r >= Nn) r = Nn - 1;                                            \
            cpa16(sb + _off + (uint32_t)n * TSTRIDE + (uint32_t)c * 16u,        \
                  Y_half + (size_t)r * 128 + c * 8);                            \
        }                                                                       \
        CPA_COMMIT();                                                           \
    } while (0)

    COPY_Y(0, blockIdx.x * 128);

    // ldmatrix addressing
    uint32_t a_row = (uint32_t)(lane & 15);
    uint32_t a_hi  = (uint32_t)(lane >> 4) * 16u;
    uint32_t a_off0 = ((uint32_t)(warp_m * 32) + a_row) * TSTRIDE + a_hi;
    uint32_t a_off1 = ((uint32_t)(warp_m * 32 + 16) + a_row) * TSTRIDE + a_hi;
    uint32_t b_row = (uint32_t)((lane & 7) + ((lane >> 4) << 3));
    uint32_t b_hi  = (uint32_t)((lane >> 3) & 1) * 16u;
    uint32_t b_off0 = ((uint32_t)(warp_n * 32) + b_row) * TSTRIDE + b_hi;
    uint32_t b_off1 = ((uint32_t)(warp_n * 32 + 16) + b_row) * TSTRIDE + b_hi;

    int rloc = warp_m * 32 + (lane >> 2);
    int nbase = warp_n * 32 + (lane & 3) * 2;

    int p = 0;
    for (int t = blockIdx.x; t < NTILES; t += NSM) {
        int base = t * 128;
        int nxt = t + NSM;

        int issued = 0;
        if (nxt < NTILES) { COPY_Y(p ^ 1, nxt * 128); issued = 1; }
        if (issued) CPA_WAIT(1); else CPA_WAIT(0);
        __syncthreads();                    // Y buf p (weights, biases) visible

        uint32_t ya = sb + T_OFF(3 + p);
        int row[4];
        bool ok[4];
#pragma unroll
        for (int j = 0; j < 4; j++) { row[j] = base + rloc + j * 8; ok[j] = row[j] < Nn; }

        // ================= phase A: acc1 = Y@W1 =================
        {
            float acc1[2][4][4];
#pragma unroll
            for (int f = 0; f < 2; f++)
#pragma unroll
                for (int ni = 0; ni < 4; ni++)
#pragma unroll
                    for (int j = 0; j < 4; j++) acc1[f][ni][j] = 0.f;

#pragma unroll
            for (int k0 = 0; k0 < 8; k0++) {
                uint32_t kb = (uint32_t)k0 * 32u;
                uint32_t yh[2][4];
                ldsm4(yh[0], ya + a_off0 + kb);
                ldsm4(yh[1], ya + a_off1 + kb);
                uint32_t bh0[4], bh1[4];
                ldsm4(bh0, sb + T_OFF(0) + b_off0 + kb);
                ldsm4(bh1, sb + T_OFF(0) + b_off1 + kb);
#pragma unroll
                for (int f = 0; f < 2; f++) {
                    mma_f16(acc1[f][0], yh[f], bh0 + 0);
                    mma_f16(acc1[f][1], yh[f], bh0 + 2);
                    mma_f16(acc1[f][2], yh[f], bh1 + 0);
                    mma_f16(acc1[f][3], yh[f], bh1 + 2);
                }
            }

            // epilogue A: A_half = acc1 + b1 (bias via smem)
#pragma unroll
            for (int f = 0; f < 2; f++)
#pragma unroll
                for (int half = 0; half < 2; half++) {
                    int j = 2 * f + half;
                    if (!ok[j]) continue;
                    __half* ap = A_half + (size_t)row[j] * 128;
#pragma unroll
                    for (int ni = 0; ni < 4; ni++) {
                        int n = nbase + ni * 8;
                        float2 v1 = *reinterpret_cast<const float2*>(smem + BIAS_OFF + n * 4);
                        *reinterpret_cast<__half2*>(ap + n) =
                            __floats2half2_rn(acc1[f][ni][half * 2 + 0] + v1.x,
                                              acc1[f][ni][half * 2 + 1] + v1.y);
                    }
                }
        }

        // ========= phase B: acc2 = Y@W2, acc3 = Y@W3 =========
        {
            float acc2[2][4][4], acc3[2][4][4];
#pragma unroll
            for (int f = 0; f < 2; f++)
#pragma unroll
                for (int ni = 0; ni < 4; ni++)
#pragma unroll
                    for (int j = 0; j < 4; j++) { acc2[f][ni][j] = 0.f; acc3[f][ni][j] = 0.f; }

#pragma unroll
            for (int k0 = 0; k0 < 8; k0++) {
                uint32_t kb = (uint32_t)k0 * 32u;
                uint32_t yh[2][4];
                ldsm4(yh[0], ya + a_off0 + kb);
                ldsm4(yh[1], ya + a_off1 + kb);
                uint32_t c2h0[4], c2h1[4], c3h0[4], c3h1[4];
                ldsm4(c2h0, sb + T_OFF(1) + b_off0 + kb);
                ldsm4(c2h1, sb + T_OFF(1) + b_off1 + kb);
                ldsm4(c3h0, sb + T_OFF(2) + b_off0 + kb);
                ldsm4(c3h1, sb + T_OFF(2) + b_off1 + kb);
#pragma unroll
                for (int f = 0; f < 2; f++) {
                    mma_f16(acc2[f][0], yh[f], c2h0 + 0);
                    mma_f16(acc2[f][1], yh[f], c2h0 + 2);
                    mma_f16(acc2[f][2], yh[f], c2h1 + 0);
                    mma_f16(acc2[f][3], yh[f], c2h1 + 2);
                    mma_f16(acc3[f][0], yh[f], c3h0 + 0);
                    mma_f16(acc3[f][1], yh[f], c3h0 + 2);
                    mma_f16(acc3[f][2], yh[f], c3h1 + 0);
                    mma_f16(acc3[f][3], yh[f], c3h1 + 2);
                }
            }

            // epilogue B: H = acc3 + b3 - deg*acc2 (bias via smem)
#pragma unroll
            for (int f = 0; f < 2; f++)
#pragma unroll
                for (int half = 0; half < 2; half++) {
                    int j = 2 * f + half;
                    if (!ok[j]) continue;
                    float dg = (float)cnt_buf[row[j]];
                    float* hp = H_buf + (size_t)row[j] * 128;
#pragma unroll
                    for (int ni = 0; ni < 4; ni++) {
                        int n = nbase + ni * 8;
                        float2 v3 = *reinterpret_cast<const float2*>(smem + BIAS_OFF + 512 + n * 4);
                        float2 o;
                        o.x = acc3[f][ni][half * 2 + 0] + v3.x - dg * acc2[f][ni][half * 2 + 0];
                        o.y = acc3[f][ni][half * 2 + 1] + v3.y - dg * acc2[f][ni][half * 2 + 1];
                        *reinterpret_cast<float2*>(hp + n) = o;
                    }
                }
        }

        __syncthreads();                    // reads of buf p done before overwrite
        p ^= 1;
    }
#undef COPY_Y
}

// --- gather: 4-deep pipelined scalar loads; overflow folded; fp32 stats ---
__global__ void gather_kernel() {
    int tid = threadIdx.x;
    int gw = (blockIdx.x * 256 + tid) >> 5;          // 12500*8 = 100000 exact
    int lane = tid & 31;
    int c = cnt_buf[gw];
    int cc = (c > CAPB) ? CAPB : c;
    const int* bk = bucket_buf + (size_t)gw * CAPB;
    const uint2* ab = reinterpret_cast<const uint2*>(A_half);
    const uint2 z = make_uint2(0u, 0u);

#define GLD(i) __ldg(ab + (size_t)__ldg(bk + (i)) * 32 + lane)

    float4 acc = make_float4(0.f, 0.f, 0.f, 0.f);
    uint2 v0 = (0 < cc) ? GLD(0) : z;
    uint2 v1 = (1 < cc) ? GLD(1) : z;
    uint2 v2 = (2 < cc) ? GLD(2) : z;
    uint2 v3 = (3 < cc) ? GLD(3) : z;

    for (int e = 0; e < cc; e += 4) {
        uint2 c0 = v0, c1 = v1, c2 = v2, c3 = v3;
        v0 = (e + 4 < cc) ? GLD(e + 4) : z;
        v1 = (e + 5 < cc) ? GLD(e + 5) : z;
        v2 = (e + 6 < cc) ? GLD(e + 6) : z;
        v3 = (e + 7 < cc) ? GLD(e + 7) : z;
        float2 a;
        a = __half22float2(*reinterpret_cast<__half2*>(&c0.x)); acc.x += a.x; acc.y += a.y;
        a = __half22float2(*reinterpret_cast<__half2*>(&c0.y)); acc.z += a.x; acc.w += a.y;
        a = __half22float2(*reinterpret_cast<__half2*>(&c1.x)); acc.x += a.x; acc.y += a.y;
        a = __half22float2(*reinterpret_cast<__half2*>(&c1.y)); acc.z += a.x; acc.w += a.y;
        a = __half22float2(*reinterpret_cast<__half2*>(&c2.x)); acc.x += a.x; acc.y += a.y;
        a = __half22float2(*reinterpret_cast<__half2*>(&c2.y)); acc.z += a.x; acc.w += a.y;
        a = __half22float2(*reinterpret_cast<__half2*>(&c3.x)); acc.x += a.x; acc.y += a.y;
        a = __half22float2(*reinterpret_cast<__half2*>(&c3.y)); acc.z += a.x; acc.w += a.y;
    }
#undef GLD

    // overflow edges for this node (ov_cnt==0 in practice; correct if not)
    if (c > CAPB) {
        int m = ov_cnt;
        if (m > MAX_OV) m = MAX_OV;
        for (int e = 0; e < m; e++) {
            if (ov_dst[e] == gw) {
                uint2 vv = __ldg(ab + (size_t)ov_src[e] * 32 + lane);
                float2 a;
                a = __half22float2(*reinterpret_cast<__half2*>(&vv.x)); acc.x += a.x; acc.y += a.y;
                a = __half22float2(*reinterpret_cast<__half2*>(&vv.y)); acc.z += a.x; acc.w += a.y;
            }
        }
    }

    float4* hp = reinterpret_cast<float4*>(H_buf + (size_t)gw * 128) + lane;
    float4 h = *hp;
    h.x += acc.x; h.y += acc.y; h.z += acc.z; h.w += acc.w;
    *hp = h;

    float s  = h.x + h.y + h.z + h.w;
    float ss = h.x * h.x + h.y * h.y + h.z * h.z + h.w * h.w;
#pragma unroll
    for (int o = 16; o > 0; o >>= 1) {
        s  += __shfl_down_sync(0xffffffffu, s, o);
        ss += __shfl_down_sync(0xffffffffu, ss, o);
    }
    __shared__ float sh[2][8];
    int w = tid >> 5;
    if (lane == 0) { sh[0][w] = s; sh[1][w] = ss; }
    __syncthreads();
    if (tid == 0) {
        float ts = 0.f, tss = 0.f;
#pragma unroll
        for (int i = 0; i < 8; i++) { ts += sh[0][i]; tss += sh[1][i]; }
        atomicAdd(&g_sum, (double)ts);
        atomicAdd(&g_sumsq, (double)tss);
    }
}

// -- normalize + affine + leaky_relu + residual + fp16 store ---------------
__global__ void final_update(const float* __restrict__ lw, const float* __restrict__ lb,
                             const float* __restrict__ yin, float* __restrict__ yout,
                             int do_split) {
    double M = (double)NDTOT;
    double mean = g_sum / M;
    double var = g_sumsq / M - mean * mean;
    if (var < 0.0) var = 0.0;
    float inv = 1.0f / ((float)sqrt(var) + 1e-5f);
    float mf = (float)mean;

    int idx = blockIdx.x * blockDim.x + threadIdx.x;
    int stride = gridDim.x * blockDim.x;
    const float4* h4 = reinterpret_cast<const float4*>(H_buf);
    const float4* y4 = reinterpret_cast<const float4*>(yin);
    float4* o4 = reinterpret_cast<float4*>(yout);
    for (int i = idx; i < NDTOT / 4; i += stride) {
        int d = (i * 4) & 127;
        float4 w = *reinterpret_cast<const float4*>(lw + d);
        float4 b = *reinterpret_cast<const float4*>(lb + d);
        float4 h = h4[i];
        float4 y = y4[i];
        float t;
        float4 o;
        t = (h.x - mf) * inv; t = t * w.x + b.x; t = (t >= 0.f) ? t : 0.01f * t; o.x = y.x + t;
        t = (h.y - mf) * inv; t = t * w.y + b.y; t = (t >= 0.f) ? t : 0.01f * t; o.y = y.y + t;
        t = (h.z - mf) * inv; t = t * w.z + b.z; t = (t >= 0.f) ? t : 0.01f * t; o.z = y.z + t;
        t = (h.w - mf) * inv; t = t * w.w + b.w; t = (t >= 0.f) ? t : 0.01f * t; o.w = y.w + t;
        o4[i] = o;
        if (do_split) {
            __half2* yp = reinterpret_cast<__half2*>(Y_half + 4 * i);
            yp[0] = __floats2half2_rn(o.x, o.y);
            yp[1] = __floats2half2_rn(o.z, o.w);
        }
    }
}

// ---------------------------------------------------------------------------
extern "C" void kernel_launch(void* const* d_in, const int* in_sizes, int n_in,
                              void* d_out, int out_size) {
    const float* y0 = (const float*)d_in[0];
    const int*   ei = (const int*)d_in[1];
    const float* W1 = (const float*)d_in[2];
    const float* b1 = (const float*)d_in[3];
    const float* W2 = (const float*)d_in[4];
    const float* W3 = (const float*)d_in[5];
    const float* b3 = (const float*)d_in[6];
    const float* lw = (const float*)d_in[7];
    const float* lb = (const float*)d_in[8];
    float* yout = (float*)d_out;

    (void)in_sizes; (void)n_in; (void)out_size;

    cudaFuncSetAttribute(gemm_fused, cudaFuncAttributeMaxDynamicSharedMemorySize, G_SMEM);

    init_kernel<<<(Nn + 255) / 256, 256>>>(ei);                            // #1
    build_prep<<<(NDTOT / 2 + 255) / 256, 256>>>(ei, y0, W1, W2, W3);      // #2

    for (int l = 0; l < Ll; l++) {
        const float* yin = (l == 0) ? y0 : yout;
        gemm_fused<<<NSM, NTHR, G_SMEM>>>(l, b1 + (size_t)l * Dd,
                                          b3 + (size_t)l * Dd);            // #3
        gather_kernel<<<(Nn + 7) / 8, 256>>>();                            // #4 = profiled (l=0)
        final_update<<<1024, 256>>>(lw + (size_t)l * Dd, lb + (size_t)l * Dd, yin, yout,
                                    (l + 1 < Ll) ? 1 : 0);
    }
}

// round 17
// speedup vs baseline: 1.1239x; 1.0395x over previous
#include <cuda_runtime.h>
#include <cuda_fp16.h>
#include <math.h>
#include <stdint.h>

#define Nn 100000
#define Ee 1600000
#define Dd 128
#define Ll 3
#define CAPB 96
#define MAX_OV 8192
#define NDTOT (Nn * Dd)
#define NTILES 782
#define NSM 148

// ---------------- device scratch ----------------
static __device__ __half A_half[NDTOT];               // lin1(y), fp16
static __device__ float H_buf[NDTOT];
static __device__ int   cnt_buf[Nn];
static __device__ int   bucket_buf[Nn * CAPB];
static __device__ int   ov_src[MAX_OV];
static __device__ int   ov_dst[MAX_OV];
static __device__ int   ov_cnt;
static __device__ int   g_is64;
static __device__ double g_sum, g_sumsq;
static __device__ __half Y_half[NDTOT];               // fp16 Y for GEMM A operand
// per layer 3 tiles [n][k] fp16: W1,W2,W3 (transposed)
static __device__ __half Wsp_buf[Ll * 3 * 128 * 128];

__device__ __forceinline__ uint32_t s2u(const void* p) {
    return (uint32_t)__cvta_generic_to_shared(p);
}

// ---------------- init ----------------
__global__ void init_kernel(const int* __restrict__ ei) {
    int i = blockIdx.x * blockDim.x + threadIdx.x;
    if (i < Nn) cnt_buf[i] = 0;
    if (i == 0) {
        ov_cnt = 0;
        int all0 = 1;
        for (int k = 0; k < 128; k++) {
            if (ei[2 * k + 1] != 0) { all0 = 0; break; }
        }
        g_is64 = all0;
    }
}

__device__ __forceinline__ int fetch_idx(const int* __restrict__ ei, int pos, int is64) {
    return is64 ? ei[2 * pos] : ei[pos];
}

// ------- build CSR buckets + convert Y + weights to fp16 ------------------
__global__ void build_prep(const int* __restrict__ ei,
                           const float* __restrict__ Y,
                           const float* __restrict__ W1,
                           const float* __restrict__ W2,
                           const float* __restrict__ W3) {
    int idx = blockIdx.x * blockDim.x + threadIdx.x;
    if (idx < Ee) {
        int is64 = g_is64;
        int src = fetch_idx(ei, idx, is64);
        int dst = fetch_idx(ei, Ee + idx, is64);
        int pos = atomicAdd(&cnt_buf[dst], 1);
        if (pos < CAPB) {
            bucket_buf[(size_t)dst * CAPB + pos] = src;
        } else {
            int o = atomicAdd(&ov_cnt, 1);
            if (o < MAX_OV) { ov_src[o] = src; ov_dst[o] = dst; }
        }
    }
    if (idx < NDTOT / 2) {
        float2 v = *reinterpret_cast<const float2*>(Y + 2 * idx);
        *reinterpret_cast<__half2*>(Y_half + 2 * idx) = __floats2half2_rn(v.x, v.y);
    }
    if (idx < Ll * 3 * 16384) {
        int lw = idx >> 14;
        int rem = idx & 16383;
        int k = rem >> 7, n = rem & 127;
        int l = lw / 3, w = lw % 3;   // w: 0=W1 1=W2 2=W3
        const float* W = (w == 0) ? W1 : (w == 1) ? W2 : W3;
        float v = W[(size_t)l * 16384 + rem];
        Wsp_buf[((size_t)l * 3 + w) * 16384 + (size_t)n * 128 + k] = __float2half_rn(v);
    }
}

// ======================= HMMA helpers ==========================
__device__ __forceinline__ void mma_f16(float* d, const uint32_t* a, const uint32_t* b) {
    asm volatile("mma.sync.aligned.m16n8k16.row.col.f32.f16.f16.f32 "
        "{%0,%1,%2,%3}, {%4,%5,%6,%7}, {%8,%9}, {%0,%1,%2,%3};"
        : "+f"(d[0]), "+f"(d[1]), "+f"(d[2]), "+f"(d[3])
        : "r"(a[0]), "r"(a[1]), "r"(a[2]), "r"(a[3]), "r"(b[0]), "r"(b[1]));
}
__device__ __forceinline__ void ldsm4(uint32_t* r, uint32_t addr) {
    asm volatile("ldmatrix.sync.aligned.m8n8.x4.shared.b16 {%0,%1,%2,%3}, [%4];"
        : "=r"(r[0]), "=r"(r[1]), "=r"(r[2]), "=r"(r[3]) : "r"(addr));
}
__device__ __forceinline__ void cpa16(uint32_t dst, const void* src) {
    asm volatile("cp.async.cg.shared.global [%0], [%1], 16;"
                 :: "r"(dst), "l"(src) : "memory");
}
#define CPA_COMMIT() asm volatile("cp.async.commit_group;" ::: "memory")
#define CPA_WAIT(n)  asm volatile("cp.async.wait_group %0;" :: "n"(n) : "memory")

#define TSTRIDE 272u
#define WT_BYTES (64u * TSTRIDE)          // half-weight tile: 64 n-rows
#define Y_BYTES  (128u * TSTRIDE)         // full Y tile
#define WT_OFF(i) ((uint32_t)(i) * WT_BYTES)
#define YB_OFF   (3u * WT_BYTES)          // 52224
#define BIAS_OFF (YB_OFF + Y_BYTES)       // 87040
#define G_SMEM   (BIAS_OFF + 1024u)       // 88064 -> 2 CTAs/SM
#define NTHR 256

// ===== persistent fused GEMM, 2 CTAs/SM, N-split halves ===================
// grid = 2*NSM; tile = blockIdx.x>>1 (+NSM stride); n_off = (blockIdx.x&1)*64
__global__ void __launch_bounds__(NTHR, 2) gemm_fused(int layer,
                                                      const float* __restrict__ b1,
                                                      const float* __restrict__ b3) {
    extern __shared__ char smem[];
    uint32_t sb = s2u(smem);
    int tid = threadIdx.x, lane = tid & 31, wid = tid >> 5;
    int warp_m = wid & 3, warp_n = wid >> 2;      // 4 x 2 warps, warp tile 32x32
    int n_off = (blockIdx.x & 1) * 64;

    if (blockIdx.x == 0 && tid == 0) { g_sum = 0.0; g_sumsq = 0.0; }

    // ---- half-weights (our 64 n-rows), one cp.async group ----
    const __half* wbp = Wsp_buf + (size_t)layer * 3 * 16384;
#pragma unroll
    for (int tIdx = 0; tIdx < 3; tIdx++) {
        const __half* g = wbp + (size_t)tIdx * 16384 + (size_t)n_off * 128;
        uint32_t off = WT_OFF(tIdx);
        for (int i = tid; i < 1024; i += NTHR) {
            int n = i >> 4, c = i & 15;
            cpa16(sb + off + (uint32_t)n * TSTRIDE + (uint32_t)c * 16u,
                  g + (size_t)n * 128 + c * 8);
        }
    }
    CPA_COMMIT();

    // ---- biases to smem (full 128, once) ----
    if (tid < 128) {
        *reinterpret_cast<float*>(smem + BIAS_OFF + tid * 4)       = __ldg(b1 + tid);
        *reinterpret_cast<float*>(smem + BIAS_OFF + 512 + tid * 4) = __ldg(b3 + tid);
    }

    // ldmatrix addressing
    uint32_t a_row = (uint32_t)(lane & 15);
    uint32_t a_hi  = (uint32_t)(lane >> 4) * 16u;
    uint32_t a_off0 = ((uint32_t)(warp_m * 32) + a_row) * TSTRIDE + a_hi;
    uint32_t a_off1 = ((uint32_t)(warp_m * 32 + 16) + a_row) * TSTRIDE + a_hi;
    uint32_t b_row = (uint32_t)((lane & 7) + ((lane >> 4) << 3));
    uint32_t b_hi  = (uint32_t)((lane >> 3) & 1) * 16u;
    uint32_t b_off0 = ((uint32_t)(warp_n * 32) + b_row) * TSTRIDE + b_hi;       // rows 0..47
    uint32_t b_off1 = ((uint32_t)(warp_n * 32 + 16) + b_row) * TSTRIDE + b_hi;  // rows 16..63

    int rloc = warp_m * 32 + (lane >> 2);
    int nbase = n_off + warp_n * 32 + (lane & 3) * 2;
    uint32_t ya = sb + YB_OFF;

    for (int t = (blockIdx.x >> 1); t < NTILES; t += NSM) {
        int base = t * 128;

        // ---- Y tile copy (single buffer; inter-CTA overlap hides wait) ----
        for (int i = tid; i < 2048; i += NTHR) {
            int n = i >> 4, c = i & 15;
            int r = base + n;
            if (r >= Nn) r = Nn - 1;
            cpa16(ya + (uint32_t)n * TSTRIDE + (uint32_t)c * 16u,
                  Y_half + (size_t)r * 128 + c * 8);
        }
        CPA_COMMIT();
        CPA_WAIT(0);
        __syncthreads();                    // Y (weights, biases) visible

        int row[4];
        bool ok[4];
#pragma unroll
        for (int j = 0; j < 4; j++) { row[j] = base + rloc + j * 8; ok[j] = row[j] < Nn; }

        // ================= phase A: acc1 = Y@W1 =================
        {
            float acc1[2][4][4];
#pragma unroll
            for (int f = 0; f < 2; f++)
#pragma unroll
                for (int ni = 0; ni < 4; ni++)
#pragma unroll
                    for (int j = 0; j < 4; j++) acc1[f][ni][j] = 0.f;

#pragma unroll
            for (int k0 = 0; k0 < 8; k0++) {
                uint32_t kb = (uint32_t)k0 * 32u;
                uint32_t yh[2][4];
                ldsm4(yh[0], ya + a_off0 + kb);
                ldsm4(yh[1], ya + a_off1 + kb);
                uint32_t bh0[4], bh1[4];
                ldsm4(bh0, sb + WT_OFF(0) + b_off0 + kb);
                ldsm4(bh1, sb + WT_OFF(0) + b_off1 + kb);
#pragma unroll
                for (int f = 0; f < 2; f++) {
                    mma_f16(acc1[f][0], yh[f], bh0 + 0);
                    mma_f16(acc1[f][1], yh[f], bh0 + 2);
                    mma_f16(acc1[f][2], yh[f], bh1 + 0);
                    mma_f16(acc1[f][3], yh[f], bh1 + 2);
                }
            }

            // epilogue A: A_half = acc1 + b1 (bias via smem)
#pragma unroll
            for (int f = 0; f < 2; f++)
#pragma unroll
                for (int half = 0; half < 2; half++) {
                    int j = 2 * f + half;
                    if (!ok[j]) continue;
                    __half* ap = A_half + (size_t)row[j] * 128;
#pragma unroll
                    for (int ni = 0; ni < 4; ni++) {
                        int n = nbase + ni * 8;
                        float2 v1 = *reinterpret_cast<const float2*>(smem + BIAS_OFF + n * 4);
                        *reinterpret_cast<__half2*>(ap + n) =
                            __floats2half2_rn(acc1[f][ni][half * 2 + 0] + v1.x,
                                              acc1[f][ni][half * 2 + 1] + v1.y);
                    }
                }
        }

        // ========= phase B: acc2 = Y@W2, acc3 = Y@W3 =========
        {
            float acc2[2][4][4], acc3[2][4][4];
#pragma unroll
            for (int f = 0; f < 2; f++)
#pragma unroll
                for (int ni = 0; ni < 4; ni++)
#pragma unroll
                    for (int j = 0; j < 4; j++) { acc2[f][ni][j] = 0.f; acc3[f][ni][j] = 0.f; }

#pragma unroll
            for (int k0 = 0; k0 < 8; k0++) {
                uint32_t kb = (uint32_t)k0 * 32u;
                uint32_t yh[2][4];
                ldsm4(yh[0], ya + a_off0 + kb);
                ldsm4(yh[1], ya + a_off1 + kb);
                uint32_t c2h0[4], c2h1[4], c3h0[4], c3h1[4];
                ldsm4(c2h0, sb + WT_OFF(1) + b_off0 + kb);
                ldsm4(c2h1, sb + WT_OFF(1) + b_off1 + kb);
                ldsm4(c3h0, sb + WT_OFF(2) + b_off0 + kb);
                ldsm4(c3h1, sb + WT_OFF(2) + b_off1 + kb);
#pragma unroll
                for (int f = 0; f < 2; f++) {
                    mma_f16(acc2[f][0], yh[f], c2h0 + 0);
                    mma_f16(acc2[f][1], yh[f], c2h0 + 2);
                    mma_f16(acc2[f][2], yh[f], c2h1 + 0);
                    mma_f16(acc2[f][3], yh[f], c2h1 + 2);
                    mma_f16(acc3[f][0], yh[f], c3h0 + 0);
                    mma_f16(acc3[f][1], yh[f], c3h0 + 2);
                    mma_f16(acc3[f][2], yh[f], c3h1 + 0);
                    mma_f16(acc3[f][3], yh[f], c3h1 + 2);
                }
            }

            // epilogue B: H = acc3 + b3 - deg*acc2 (bias via smem)
#pragma unroll
            for (int f = 0; f < 2; f++)
#pragma unroll
                for (int half = 0; half < 2; half++) {
                    int j = 2 * f + half;
                    if (!ok[j]) continue;
                    float dg = (float)cnt_buf[row[j]];
                    float* hp = H_buf + (size_t)row[j] * 128;
#pragma unroll
                    for (int ni = 0; ni < 4; ni++) {
                        int n = nbase + ni * 8;
                        float2 v3 = *reinterpret_cast<const float2*>(smem + BIAS_OFF + 512 + n * 4);
                        float2 o;
                        o.x = acc3[f][ni][half * 2 + 0] + v3.x - dg * acc2[f][ni][half * 2 + 0];
                        o.y = acc3[f][ni][half * 2 + 1] + v3.y - dg * acc2[f][ni][half * 2 + 1];
                        *reinterpret_cast<float2*>(hp + n) = o;
                    }
                }
        }

        __syncthreads();                    // reads of Y done before next overwrite
    }
}

// --- gather: 4-deep pipelined scalar loads; overflow folded; fp32 stats ---
__global__ void gather_kernel() {
    int tid = threadIdx.x;
    int gw = (blockIdx.x * 256 + tid) >> 5;          // 12500*8 = 100000 exact
    int lane = tid & 31;
    int c = cnt_buf[gw];
    int cc = (c > CAPB) ? CAPB : c;
    const int* bk = bucket_buf + (size_t)gw * CAPB;
    const uint2* ab = reinterpret_cast<const uint2*>(A_half);
    const uint2 z = make_uint2(0u, 0u);

#define GLD(i) __ldg(ab + (size_t)__ldg(bk + (i)) * 32 + lane)

    float4 acc = make_float4(0.f, 0.f, 0.f, 0.f);
    uint2 v0 = (0 < cc) ? GLD(0) : z;
    uint2 v1 = (1 < cc) ? GLD(1) : z;
    uint2 v2 = (2 < cc) ? GLD(2) : z;
    uint2 v3 = (3 < cc) ? GLD(3) : z;

    for (int e = 0; e < cc; e += 4) {
        uint2 c0 = v0, c1 = v1, c2 = v2, c3 = v3;
        v0 = (e + 4 < cc) ? GLD(e + 4) : z;
        v1 = (e + 5 < cc) ? GLD(e + 5) : z;
        v2 = (e + 6 < cc) ? GLD(e + 6) : z;
        v3 = (e + 7 < cc) ? GLD(e + 7) : z;
        float2 a;
        a = __half22float2(*reinterpret_cast<__half2*>(&c0.x)); acc.x += a.x; acc.y += a.y;
        a = __half22float2(*reinterpret_cast<__half2*>(&c0.y)); acc.z += a.x; acc.w += a.y;
        a = __half22float2(*reinterpret_cast<__half2*>(&c1.x)); acc.x += a.x; acc.y += a.y;
        a = __half22float2(*reinterpret_cast<__half2*>(&c1.y)); acc.z += a.x; acc.w += a.y;
        a = __half22float2(*reinterpret_cast<__half2*>(&c2.x)); acc.x += a.x; acc.y += a.y;
        a = __half22float2(*reinterpret_cast<__half2*>(&c2.y)); acc.z += a.x; acc.w += a.y;
        a = __half22float2(*reinterpret_cast<__half2*>(&c3.x)); acc.x += a.x; acc.y += a.y;
        a = __half22float2(*reinterpret_cast<__half2*>(&c3.y)); acc.z += a.x; acc.w += a.y;
    }
#undef GLD

    // overflow edges for this node (ov_cnt==0 in practice; correct if not)
    if (c > CAPB) {
        int m = ov_cnt;
        if (m > MAX_OV) m = MAX_OV;
        for (int e = 0; e < m; e++) {
            if (ov_dst[e] == gw) {
                uint2 vv = __ldg(ab + (size_t)ov_src[e] * 32 + lane);
                float2 a;
                a = __half22float2(*reinterpret_cast<__half2*>(&vv.x)); acc.x += a.x; acc.y += a.y;
                a = __half22float2(*reinterpret_cast<__half2*>(&vv.y)); acc.z += a.x; acc.w += a.y;
            }
        }
    }

    float4* hp = reinterpret_cast<float4*>(H_buf + (size_t)gw * 128) + lane;
    float4 h = *hp;
    h.x += acc.x; h.y += acc.y; h.z += acc.z; h.w += acc.w;
    *hp = h;

    float s  = h.x + h.y + h.z + h.w;
    float ss = h.x * h.x + h.y * h.y + h.z * h.z + h.w * h.w;
#pragma unroll
    for (int o = 16; o > 0; o >>= 1) {
        s  += __shfl_down_sync(0xffffffffu, s, o);
        ss += __shfl_down_sync(0xffffffffu, ss, o);
    }
    __shared__ float sh[2][8];
    int w = tid >> 5;
    if (lane == 0) { sh[0][w] = s; sh[1][w] = ss; }
    __syncthreads();
    if (tid == 0) {
        float ts = 0.f, tss = 0.f;
#pragma unroll
        for (int i = 0; i < 8; i++) { ts += sh[0][i]; tss += sh[1][i]; }
        atomicAdd(&g_sum, (double)ts);
        atomicAdd(&g_sumsq, (double)tss);
    }
}

// -- normalize + affine + leaky_relu + residual + fp16 store ---------------
__global__ void final_update(const float* __restrict__ lw, const float* __restrict__ lb,
                             const float* __restrict__ yin, float* __restrict__ yout,
                             int do_split) {
    double M = (double)NDTOT;
    double mean = g_sum / M;
    double var = g_sumsq / M - mean * mean;
    if (var < 0.0) var = 0.0;
    float inv = 1.0f / ((float)sqrt(var) + 1e-5f);
    float mf = (float)mean;

    int idx = blockIdx.x * blockDim.x + threadIdx.x;
    int stride = gridDim.x * blockDim.x;
    const float4* h4 = reinterpret_cast<const float4*>(H_buf);
    const float4* y4 = reinterpret_cast<const float4*>(yin);
    float4* o4 = reinterpret_cast<float4*>(yout);
    for (int i = idx; i < NDTOT / 4; i += stride) {
        int d = (i * 4) & 127;
        float4 w = *reinterpret_cast<const float4*>(lw + d);
        float4 b = *reinterpret_cast<const float4*>(lb + d);
        float4 h = h4[i];
        float4 y = y4[i];
        float t;
        float4 o;
        t = (h.x - mf) * inv; t = t * w.x + b.x; t = (t >= 0.f) ? t : 0.01f * t; o.x = y.x + t;
        t = (h.y - mf) * inv; t = t * w.y + b.y; t = (t >= 0.f) ? t : 0.01f * t; o.y = y.y + t;
        t = (h.z - mf) * inv; t = t * w.z + b.z; t = (t >= 0.f) ? t : 0.01f * t; o.z = y.z + t;
        t = (h.w - mf) * inv; t = t * w.w + b.w; t = (t >= 0.f) ? t : 0.01f * t; o.w = y.w + t;
        o4[i] = o;
        if (do_split) {
            __half2* yp = reinterpret_cast<__half2*>(Y_half + 4 * i);
            yp[0] = __floats2half2_rn(o.x, o.y);
            yp[1] = __floats2half2_rn(o.z, o.w);
        }
    }
}

// ---------------------------------------------------------------------------
extern "C" void kernel_launch(void* const* d_in, const int* in_sizes, int n_in,
                              void* d_out, int out_size) {
    const float* y0 = (const float*)d_in[0];
    const int*   ei = (const int*)d_in[1];
    const float* W1 = (const float*)d_in[2];
    const float* b1 = (const float*)d_in[3];
    const float* W2 = (const float*)d_in[4];
    const float* W3 = (const float*)d_in[5];
    const float* b3 = (const float*)d_in[6];
    const float* lw = (const float*)d_in[7];
    const float* lb = (const float*)d_in[8];
    float* yout = (float*)d_out;

    (void)in_sizes; (void)n_in; (void)out_size;

    cudaFuncSetAttribute(gemm_fused, cudaFuncAttributeMaxDynamicSharedMemorySize, G_SMEM);

    init_kernel<<<(Nn + 255) / 256, 256>>>(ei);                            // #1
    build_prep<<<(NDTOT / 2 + 255) / 256, 256>>>(ei, y0, W1, W2, W3);      // #2

    for (int l = 0; l < Ll; l++) {
        const float* yin = (l == 0) ? y0 : yout;
        gemm_fused<<<2 * NSM, NTHR, G_SMEM>>>(l, b1 + (size_t)l * Dd,
                                              b3 + (size_t)l * Dd);        // #3
        gather_kernel<<<(Nn + 7) / 8, 256>>>();                            // #4 = profiled (l=0)
        final_update<<<1024, 256>>>(lw + (size_t)l * Dd, lb + (size_t)l * Dd, yin, yout,
                                    (l + 1 < Ll) ? 1 : 0);
    }
}